// round 6
// baseline (speedup 1.0000x reference)
#include <cuda_runtime.h>

// LIF constant-current encoder, closed-form time-split, plain write-back stores.
// x: [N] fp32 (N = 512*512). out: voltages [128*N] then spikes [128*N], fp32.
// v_t = x(1 - 0.9^t) between resets; x <= 1 never spikes (strict threshold),
// so the whole trajectory is closed-form with z == 0. x > 1 uses exact replay.
// R6 change: drop __stcs — let L2 write-back buffer the stream instead of
// evict-first, testing whether eager DRAM drain was throttling the LTS.

#define SEQ_LENGTH 128
#define CHUNK      16
#define NCHUNKS    (SEQ_LENGTH / CHUNK)
#define ALPHA      0.1f
#define DECAY      0.9f
#define DECAY_CHUNK 0.18530201888518410f  // 0.9^16
#define V_TH       1.0f

__device__ __forceinline__ void lif_step(float4& v, const float4& xv, float4& z) {
    v.x = fmaf(ALPHA, xv.x - v.x, v.x);
    v.y = fmaf(ALPHA, xv.y - v.y, v.y);
    v.z = fmaf(ALPHA, xv.z - v.z, v.z);
    v.w = fmaf(ALPHA, xv.w - v.w, v.w);
    z.x = (v.x > V_TH) ? 1.f : 0.f;
    z.y = (v.y > V_TH) ? 1.f : 0.f;
    z.z = (v.z > V_TH) ? 1.f : 0.f;
    z.w = (v.w > V_TH) ? 1.f : 0.f;
    v.x = (z.x != 0.f) ? 0.f : v.x;
    v.y = (z.y != 0.f) ? 0.f : v.y;
    v.z = (z.z != 0.f) ? 0.f : v.z;
    v.w = (z.w != 0.f) ? 0.f : v.w;
}

__global__ __launch_bounds__(256)
void lif_encoder_kernel(const float* __restrict__ x,
                        float* __restrict__ out,
                        int n4 /* N/4 */, int n /* N */) {
    int i = blockIdx.x * blockDim.x + threadIdx.x;
    if (i >= n4) return;
    int t0 = blockIdx.y * CHUNK;

    float4 xv = reinterpret_cast<const float4*>(x)[i];

    float4* vp = reinterpret_cast<float4*>(out) + (size_t)t0 * n4 + i;
    float4* zp = reinterpret_cast<float4*>(out + (size_t)SEQ_LENGTH * n)
                 + (size_t)t0 * n4 + i;

    float xmax = fmaxf(fmaxf(xv.x, xv.y), fmaxf(xv.z, xv.w));

    if (xmax <= 1.0f) {
        // Fast path: no spikes ever. v_t = x * (1 - 0.9^t), z = 0.
        float p = 1.0f;
        #pragma unroll 1
        for (unsigned c = blockIdx.y; c > 0; --c) p *= (float)DECAY_CHUNK;

        const float4 zero = make_float4(0.f, 0.f, 0.f, 0.f);
        #pragma unroll
        for (int t = 0; t < CHUNK; ++t) {
            p *= DECAY;                            // p = 0.9^(t0+t+1)
            float4 v;
            v.x = fmaf(-p, xv.x, xv.x);
            v.y = fmaf(-p, xv.y, xv.y);
            v.z = fmaf(-p, xv.z, xv.z);
            v.w = fmaf(-p, xv.w, xv.w);
            *vp = v;
            *zp = zero;
            vp += n4;
            zp += n4;
        }
    } else {
        // General path: exact replay recurrence (spiking possible).
        float4 v = make_float4(0.f, 0.f, 0.f, 0.f);
        float4 z;
        for (int t = 0; t < t0; ++t)
            lif_step(v, xv, z);
        #pragma unroll
        for (int t = 0; t < CHUNK; ++t) {
            lif_step(v, xv, z);
            *vp = v;
            *zp = z;
            vp += n4;
            zp += n4;
        }
    }
}

extern "C" void kernel_launch(void* const* d_in, const int* in_sizes, int n_in,
                              void* d_out, int out_size) {
    const float* x = (const float*)d_in[0];
    float* out = (float*)d_out;
    int n = in_sizes[0];       // 262144
    int n4 = n / 4;            // 65536

    dim3 block(256);
    dim3 grid((n4 + 255) / 256, NCHUNKS);
    lif_encoder_kernel<<<grid, block>>>(x, out, n4, n);
}

// round 7
// speedup vs baseline: 1.0988x; 1.0988x over previous
#include <cuda_runtime.h>

// LIF constant-current encoder, closed-form, 16 time-chunks of 8 steps.
// x: [N] fp32 (N = 512*512). out: voltages [128*N] then spikes [128*N], fp32.
// v_t = x(1 - 0.9^t) between resets; x <= 1 never spikes (strict threshold),
// so trajectory is closed-form with z == 0. x > 1 uses exact replay.
// R7: CHUNK 16 -> 8 (4096 CTAs) — free extra store concurrency since the
// closed form has no replay cost. Keep .cs streaming stores.

#define SEQ_LENGTH 128
#define CHUNK      8
#define NCHUNKS    (SEQ_LENGTH / CHUNK)
#define ALPHA      0.1f
#define DECAY      0.9f
#define DECAY_CHUNK 0.4304672100000f     // 0.9^8
#define V_TH       1.0f

__device__ __forceinline__ void lif_step(float4& v, const float4& xv, float4& z) {
    v.x = fmaf(ALPHA, xv.x - v.x, v.x);
    v.y = fmaf(ALPHA, xv.y - v.y, v.y);
    v.z = fmaf(ALPHA, xv.z - v.z, v.z);
    v.w = fmaf(ALPHA, xv.w - v.w, v.w);
    z.x = (v.x > V_TH) ? 1.f : 0.f;
    z.y = (v.y > V_TH) ? 1.f : 0.f;
    z.z = (v.z > V_TH) ? 1.f : 0.f;
    z.w = (v.w > V_TH) ? 1.f : 0.f;
    v.x = (z.x != 0.f) ? 0.f : v.x;
    v.y = (z.y != 0.f) ? 0.f : v.y;
    v.z = (z.z != 0.f) ? 0.f : v.z;
    v.w = (z.w != 0.f) ? 0.f : v.w;
}

__global__ __launch_bounds__(256)
void lif_encoder_kernel(const float* __restrict__ x,
                        float* __restrict__ out,
                        int n4 /* N/4 */, int n /* N */) {
    int i = blockIdx.x * blockDim.x + threadIdx.x;
    if (i >= n4) return;
    int t0 = blockIdx.y * CHUNK;

    float4 xv = reinterpret_cast<const float4*>(x)[i];

    float4* vp = reinterpret_cast<float4*>(out) + (size_t)t0 * n4 + i;
    float4* zp = reinterpret_cast<float4*>(out + (size_t)SEQ_LENGTH * n)
                 + (size_t)t0 * n4 + i;

    float xmax = fmaxf(fmaxf(xv.x, xv.y), fmaxf(xv.z, xv.w));

    if (xmax <= 1.0f) {
        // Fast path: no spikes ever. v_t = x * (1 - 0.9^t), z = 0.
        // p = 0.9^t0 = (0.9^CHUNK)^blockIdx.y  (uniform scalar, <= 15 muls)
        float p = 1.0f;
        #pragma unroll 1
        for (unsigned c = blockIdx.y; c > 0; --c) p *= (float)DECAY_CHUNK;

        const float4 zero = make_float4(0.f, 0.f, 0.f, 0.f);
        #pragma unroll
        for (int t = 0; t < CHUNK; ++t) {
            __stcs(zp, zero);                      // constant reg — issue first
            p *= DECAY;                            // p = 0.9^(t0+t+1)
            float4 v;
            v.x = fmaf(-p, xv.x, xv.x);
            v.y = fmaf(-p, xv.y, xv.y);
            v.z = fmaf(-p, xv.z, xv.z);
            v.w = fmaf(-p, xv.w, xv.w);
            __stcs(vp, v);
            vp += n4;
            zp += n4;
        }
    } else {
        // General path: exact replay recurrence (spiking possible).
        float4 v = make_float4(0.f, 0.f, 0.f, 0.f);
        float4 z;
        for (int t = 0; t < t0; ++t)
            lif_step(v, xv, z);
        #pragma unroll
        for (int t = 0; t < CHUNK; ++t) {
            lif_step(v, xv, z);
            __stcs(vp, v);
            __stcs(zp, z);
            vp += n4;
            zp += n4;
        }
    }
}

extern "C" void kernel_launch(void* const* d_in, const int* in_sizes, int n_in,
                              void* d_out, int out_size) {
    const float* x = (const float*)d_in[0];
    float* out = (float*)d_out;
    int n = in_sizes[0];       // 262144
    int n4 = n / 4;            // 65536

    dim3 block(256);
    dim3 grid((n4 + 255) / 256, NCHUNKS);
    lif_encoder_kernel<<<grid, block>>>(x, out, n4, n);
}

// round 8
// speedup vs baseline: 1.1099x; 1.0101x over previous
#include <cuda_runtime.h>

// LIF constant-current encoder, closed-form, 32 time-chunks of 4 steps.
// x: [N] fp32 (N = 512*512). out: voltages [128*N] then spikes [128*N], fp32.
// v_t = x(1 - 0.9^t) between resets; x <= 1 never spikes (strict threshold),
// so trajectory is closed-form with z == 0. x > 1 uses exact replay.
// R8: CHUNK 8 -> 4 (8192 CTAs) — one more free doubling of store concurrency.

#define SEQ_LENGTH 128
#define CHUNK      4
#define NCHUNKS    (SEQ_LENGTH / CHUNK)
#define ALPHA      0.1f
#define DECAY      0.9f
#define DECAY_CHUNK 0.6561f              // 0.9^4
#define V_TH       1.0f

__device__ __forceinline__ void lif_step(float4& v, const float4& xv, float4& z) {
    v.x = fmaf(ALPHA, xv.x - v.x, v.x);
    v.y = fmaf(ALPHA, xv.y - v.y, v.y);
    v.z = fmaf(ALPHA, xv.z - v.z, v.z);
    v.w = fmaf(ALPHA, xv.w - v.w, v.w);
    z.x = (v.x > V_TH) ? 1.f : 0.f;
    z.y = (v.y > V_TH) ? 1.f : 0.f;
    z.z = (v.z > V_TH) ? 1.f : 0.f;
    z.w = (v.w > V_TH) ? 1.f : 0.f;
    v.x = (z.x != 0.f) ? 0.f : v.x;
    v.y = (z.y != 0.f) ? 0.f : v.y;
    v.z = (z.z != 0.f) ? 0.f : v.z;
    v.w = (z.w != 0.f) ? 0.f : v.w;
}

__global__ __launch_bounds__(256)
void lif_encoder_kernel(const float* __restrict__ x,
                        float* __restrict__ out,
                        int n4 /* N/4 */, int n /* N */) {
    int i = blockIdx.x * blockDim.x + threadIdx.x;
    if (i >= n4) return;
    int t0 = blockIdx.y * CHUNK;

    float4 xv = reinterpret_cast<const float4*>(x)[i];

    float4* vp = reinterpret_cast<float4*>(out) + (size_t)t0 * n4 + i;
    float4* zp = reinterpret_cast<float4*>(out + (size_t)SEQ_LENGTH * n)
                 + (size_t)t0 * n4 + i;

    float xmax = fmaxf(fmaxf(xv.x, xv.y), fmaxf(xv.z, xv.w));

    if (xmax <= 1.0f) {
        // Fast path: no spikes ever. v_t = x * (1 - 0.9^t), z = 0.
        // p = 0.9^t0 = (0.9^CHUNK)^blockIdx.y  (uniform scalar, <= 31 muls)
        float p = 1.0f;
        #pragma unroll 1
        for (unsigned c = blockIdx.y; c > 0; --c) p *= (float)DECAY_CHUNK;

        const float4 zero = make_float4(0.f, 0.f, 0.f, 0.f);
        #pragma unroll
        for (int t = 0; t < CHUNK; ++t) {
            __stcs(zp, zero);                      // constant reg — issue first
            p *= DECAY;                            // p = 0.9^(t0+t+1)
            float4 v;
            v.x = fmaf(-p, xv.x, xv.x);
            v.y = fmaf(-p, xv.y, xv.y);
            v.z = fmaf(-p, xv.z, xv.z);
            v.w = fmaf(-p, xv.w, xv.w);
            __stcs(vp, v);
            vp += n4;
            zp += n4;
        }
    } else {
        // General path: exact replay recurrence (spiking possible).
        float4 v = make_float4(0.f, 0.f, 0.f, 0.f);
        float4 z;
        for (int t = 0; t < t0; ++t)
            lif_step(v, xv, z);
        #pragma unroll
        for (int t = 0; t < CHUNK; ++t) {
            lif_step(v, xv, z);
            __stcs(vp, v);
            __stcs(zp, z);
            vp += n4;
            zp += n4;
        }
    }
}

extern "C" void kernel_launch(void* const* d_in, const int* in_sizes, int n_in,
                              void* d_out, int out_size) {
    const float* x = (const float*)d_in[0];
    float* out = (float*)d_out;
    int n = in_sizes[0];       // 262144
    int n4 = n / 4;            // 65536

    dim3 block(256);
    dim3 grid((n4 + 255) / 256, NCHUNKS);
    lif_encoder_kernel<<<grid, block>>>(x, out, n4, n);
}

// round 9
// speedup vs baseline: 1.1302x; 1.0183x over previous
#include <cuda_runtime.h>

// LIF constant-current encoder — fully parallel closed form (CHUNK = 1).
// x: [N] fp32 (N = 512*512). out: voltages [128*N] then spikes [128*N], fp32.
// v_t = x(1 - 0.9^t) between resets; x <= 1 never spikes (strict threshold
// v - 1 > 0 and v_t < x), so every output is closed-form with z == 0.
// R9: grid.y = t (128 slices). Each thread writes one float4 of v and z for
// its (t, i) directly; p = 0.9^(t+1) via one MUFU exp2. No serial prologue.
// x > 1 (absent in this dataset) falls back to exact per-thread replay.

#define SEQ_LENGTH 128
#define ALPHA      0.1f
#define DECAY      0.9f
#define LOG2_DECAY (-0.15200309344504997f)   // log2(0.9)
#define V_TH       1.0f

__device__ __forceinline__ void lif_step(float4& v, const float4& xv, float4& z) {
    v.x = fmaf(ALPHA, xv.x - v.x, v.x);
    v.y = fmaf(ALPHA, xv.y - v.y, v.y);
    v.z = fmaf(ALPHA, xv.z - v.z, v.z);
    v.w = fmaf(ALPHA, xv.w - v.w, v.w);
    z.x = (v.x > V_TH) ? 1.f : 0.f;
    z.y = (v.y > V_TH) ? 1.f : 0.f;
    z.z = (v.z > V_TH) ? 1.f : 0.f;
    z.w = (v.w > V_TH) ? 1.f : 0.f;
    v.x = (z.x != 0.f) ? 0.f : v.x;
    v.y = (z.y != 0.f) ? 0.f : v.y;
    v.z = (z.z != 0.f) ? 0.f : v.z;
    v.w = (z.w != 0.f) ? 0.f : v.w;
}

__global__ __launch_bounds__(256)
void lif_encoder_kernel(const float* __restrict__ x,
                        float* __restrict__ out,
                        int n4 /* N/4 */, int n /* N */) {
    int i = blockIdx.x * blockDim.x + threadIdx.x;
    if (i >= n4) return;
    int t = blockIdx.y;                  // 0 .. SEQ_LENGTH-1

    float4 xv = reinterpret_cast<const float4*>(x)[i];

    float4* vp = reinterpret_cast<float4*>(out) + (size_t)t * n4 + i;
    float4* zp = reinterpret_cast<float4*>(out + (size_t)SEQ_LENGTH * n)
                 + (size_t)t * n4 + i;

    float xmax = fmaxf(fmaxf(xv.x, xv.y), fmaxf(xv.z, xv.w));

    if (xmax <= 1.0f) {
        // Closed form: v_t = x * (1 - 0.9^(t+1)), z = 0.
        float p = exp2f((float)(t + 1) * LOG2_DECAY);   // 0.9^(t+1)
        const float4 zero = make_float4(0.f, 0.f, 0.f, 0.f);
        __stcs(zp, zero);
        float4 v;
        v.x = fmaf(-p, xv.x, xv.x);
        v.y = fmaf(-p, xv.y, xv.y);
        v.z = fmaf(-p, xv.z, xv.z);
        v.w = fmaf(-p, xv.w, xv.w);
        __stcs(vp, v);
    } else {
        // Exact replay up to and including step t (spiking possible).
        float4 v = make_float4(0.f, 0.f, 0.f, 0.f);
        float4 z;
        for (int s = 0; s <= t; ++s)
            lif_step(v, xv, z);
        __stcs(vp, v);
        __stcs(zp, z);
    }
}

extern "C" void kernel_launch(void* const* d_in, const int* in_sizes, int n_in,
                              void* d_out, int out_size) {
    const float* x = (const float*)d_in[0];
    float* out = (float*)d_out;
    int n = in_sizes[0];       // 262144
    int n4 = n / 4;            // 65536

    dim3 block(256);
    dim3 grid((n4 + 255) / 256, SEQ_LENGTH);
    lif_encoder_kernel<<<grid, block>>>(x, out, n4, n);
}

// round 12
// speedup vs baseline: 1.1401x; 1.0088x over previous
#include <cuda_runtime.h>

// LIF constant-current encoder — closed form, 64 time-chunks of 2 steps.
// x: [N] fp32 (N = 512*512). out: voltages [128*N] then spikes [128*N], fp32.
// Recurrence v_{t+1} = 0.9 v + 0.1 x from v=0 gives v_t = x(1 - 0.9^t)
// between resets; threshold is strict (v - 1 > 0) and v_t < x, so x <= 1
// never spikes: the whole trajectory is closed-form with z == 0.
// CHUNK=2 keeps massive store concurrency (16384 CTAs) while amortizing the
// per-CTA x load / branch / exp2f over two stores. x > 1 uses exact replay.

#define SEQ_LENGTH 128
#define CHUNK      2
#define NCHUNKS    (SEQ_LENGTH / CHUNK)
#define ALPHA      0.1f
#define DECAY      0.9f
#define LOG2_DECAY (-0.15200309344504997f)   // log2(0.9)
#define V_TH       1.0f

__device__ __forceinline__ void lif_step(float4& v, const float4& xv, float4& z) {
    v.x = fmaf(ALPHA, xv.x - v.x, v.x);
    v.y = fmaf(ALPHA, xv.y - v.y, v.y);
    v.z = fmaf(ALPHA, xv.z - v.z, v.z);
    v.w = fmaf(ALPHA, xv.w - v.w, v.w);
    z.x = (v.x > V_TH) ? 1.f : 0.f;
    z.y = (v.y > V_TH) ? 1.f : 0.f;
    z.z = (v.z > V_TH) ? 1.f : 0.f;
    z.w = (v.w > V_TH) ? 1.f : 0.f;
    v.x = (z.x != 0.f) ? 0.f : v.x;
    v.y = (z.y != 0.f) ? 0.f : v.y;
    v.z = (z.z != 0.f) ? 0.f : v.z;
    v.w = (z.w != 0.f) ? 0.f : v.w;
}

__global__ __launch_bounds__(256)
void lif_encoder_kernel(const float* __restrict__ x,
                        float* __restrict__ out,
                        int n4 /* N/4 */, int n /* N */) {
    int i = blockIdx.x * blockDim.x + threadIdx.x;
    if (i >= n4) return;
    const int t0 = blockIdx.y * CHUNK;   // 0, 2, ... 126

    const float4 xv = reinterpret_cast<const float4*>(x)[i];

    float4* vp = reinterpret_cast<float4*>(out) + (size_t)t0 * n4 + i;
    float4* zp = reinterpret_cast<float4*>(out + (size_t)SEQ_LENGTH * n)
                 + (size_t)t0 * n4 + i;

    const float xmax = fmaxf(fmaxf(xv.x, xv.y), fmaxf(xv.z, xv.w));

    if (xmax <= 1.0f) {
        // Fast path: no spikes ever. v_t = x * (1 - 0.9^(t+1)), z = 0.
        float p = exp2f((float)(t0 + 1) * LOG2_DECAY);   // 0.9^(t0+1), one MUFU
        const float4 zero = make_float4(0.f, 0.f, 0.f, 0.f);

        #pragma unroll
        for (int t = 0; t < CHUNK; ++t) {
            __stcs(zp, zero);
            float4 v;
            v.x = fmaf(-p, xv.x, xv.x);
            v.y = fmaf(-p, xv.y, xv.y);
            v.z = fmaf(-p, xv.z, xv.z);
            v.w = fmaf(-p, xv.w, xv.w);
            __stcs(vp, v);
            p *= DECAY;
            vp += n4;
            zp += n4;
        }
    } else {
        // General path: exact replay recurrence (spiking possible).
        float4 v = make_float4(0.f, 0.f, 0.f, 0.f);
        float4 z;
        #pragma unroll 1
        for (int s = 0; s < t0; ++s)
            lif_step(v, xv, z);
        #pragma unroll
        for (int t = 0; t < CHUNK; ++t) {
            lif_step(v, xv, z);
            __stcs(vp, v);
            __stcs(zp, z);
            vp += n4;
            zp += n4;
        }
    }
}

extern "C" void kernel_launch(void* const* d_in, const int* in_sizes, int n_in,
                              void* d_out, int out_size) {
    const float* x = (const float*)d_in[0];
    float* out = (float*)d_out;
    int n = in_sizes[0];       // 262144
    int n4 = n / 4;            // 65536

    dim3 block(256);
    dim3 grid((n4 + 255) / 256, NCHUNKS);
    lif_encoder_kernel<<<grid, block>>>(x, out, n4, n);
}

// round 14
// speedup vs baseline: 1.1493x; 1.0081x over previous
#include <cuda_runtime.h>

// LIF constant-current encoder — closed form, 64 time-chunks of 2 steps.
// x: [N] fp32 (N = 512*512). out: voltages [128*N] then spikes [128*N], fp32.
// v_t = x(1 - 0.9^t) between resets; strict threshold (v - 1 > 0) and
// v_t < x mean x <= 1 never spikes: whole trajectory closed-form, z == 0.
// R13: block 256 -> 128 (32768 CTAs) — finer scheduling granularity for
// smoother wave transitions; everything else identical to the R12 winner.

#define SEQ_LENGTH 128
#define CHUNK      2
#define NCHUNKS    (SEQ_LENGTH / CHUNK)
#define ALPHA      0.1f
#define DECAY      0.9f
#define LOG2_DECAY (-0.15200309344504997f)   // log2(0.9)
#define V_TH       1.0f
#define BLOCK      128

__device__ __forceinline__ void lif_step(float4& v, const float4& xv, float4& z) {
    v.x = fmaf(ALPHA, xv.x - v.x, v.x);
    v.y = fmaf(ALPHA, xv.y - v.y, v.y);
    v.z = fmaf(ALPHA, xv.z - v.z, v.z);
    v.w = fmaf(ALPHA, xv.w - v.w, v.w);
    z.x = (v.x > V_TH) ? 1.f : 0.f;
    z.y = (v.y > V_TH) ? 1.f : 0.f;
    z.z = (v.z > V_TH) ? 1.f : 0.f;
    z.w = (v.w > V_TH) ? 1.f : 0.f;
    v.x = (z.x != 0.f) ? 0.f : v.x;
    v.y = (z.y != 0.f) ? 0.f : v.y;
    v.z = (z.z != 0.f) ? 0.f : v.z;
    v.w = (z.w != 0.f) ? 0.f : v.w;
}

__global__ __launch_bounds__(BLOCK)
void lif_encoder_kernel(const float* __restrict__ x,
                        float* __restrict__ out,
                        int n4 /* N/4 */, int n /* N */) {
    int i = blockIdx.x * blockDim.x + threadIdx.x;
    if (i >= n4) return;
    const int t0 = blockIdx.y * CHUNK;   // 0, 2, ... 126

    const float4 xv = reinterpret_cast<const float4*>(x)[i];

    float4* vp = reinterpret_cast<float4*>(out) + (size_t)t0 * n4 + i;
    float4* zp = reinterpret_cast<float4*>(out + (size_t)SEQ_LENGTH * n)
                 + (size_t)t0 * n4 + i;

    const float xmax = fmaxf(fmaxf(xv.x, xv.y), fmaxf(xv.z, xv.w));

    if (xmax <= 1.0f) {
        // Fast path: no spikes ever. v_t = x * (1 - 0.9^(t+1)), z = 0.
        float p = exp2f((float)(t0 + 1) * LOG2_DECAY);   // 0.9^(t0+1), one MUFU
        const float4 zero = make_float4(0.f, 0.f, 0.f, 0.f);

        #pragma unroll
        for (int t = 0; t < CHUNK; ++t) {
            __stcs(zp, zero);
            float4 v;
            v.x = fmaf(-p, xv.x, xv.x);
            v.y = fmaf(-p, xv.y, xv.y);
            v.z = fmaf(-p, xv.z, xv.z);
            v.w = fmaf(-p, xv.w, xv.w);
            __stcs(vp, v);
            p *= DECAY;
            vp += n4;
            zp += n4;
        }
    } else {
        // General path: exact replay recurrence (spiking possible).
        float4 v = make_float4(0.f, 0.f, 0.f, 0.f);
        float4 z;
        #pragma unroll 1
        for (int s = 0; s < t0; ++s)
            lif_step(v, xv, z);
        #pragma unroll
        for (int t = 0; t < CHUNK; ++t) {
            lif_step(v, xv, z);
            __stcs(vp, v);
            __stcs(zp, z);
            vp += n4;
            zp += n4;
        }
    }
}

extern "C" void kernel_launch(void* const* d_in, const int* in_sizes, int n_in,
                              void* d_out, int out_size) {
    const float* x = (const float*)d_in[0];
    float* out = (float*)d_out;
    int n = in_sizes[0];       // 262144
    int n4 = n / 4;            // 65536

    dim3 block(BLOCK);
    dim3 grid((n4 + BLOCK - 1) / BLOCK, NCHUNKS);
    lif_encoder_kernel<<<grid, block>>>(x, out, n4, n);
}

// round 16
// speedup vs baseline: 1.1568x; 1.0065x over previous
#include <cuda_runtime.h>

// LIF constant-current encoder — closed form, de-interleaved v / z streams.
// x: [N] fp32 (N = 512*512). out: voltages [128*N] then spikes [128*N], fp32.
// v_t = x(1 - 0.9^t) between resets; strict threshold (v - 1 > 0) and
// v_t < x mean x <= 1 never spikes: trajectory closed-form, z == 0.
// grid.y = 2*NCHUNKS. y < NCHUNKS -> CTA writes only a voltage chunk;
// y >= NCHUNKS -> CTA writes only a spike chunk (pure zero-fill fast path).
// Each CTA emits one contiguous store stream for DRAM row locality.
// x > 1 (absent in this dataset) falls back to exact replay in both roles.

#define SEQ_LENGTH 128
#define CHUNK      2
#define NCHUNKS    (SEQ_LENGTH / CHUNK)
#define ALPHA      0.1f
#define DECAY      0.9f
#define LOG2_DECAY (-0.15200309344504997f)   // log2(0.9)
#define V_TH       1.0f
#define BLOCK      128

__device__ __forceinline__ void lif_step(float4& v, const float4& xv, float4& z) {
    v.x = fmaf(ALPHA, xv.x - v.x, v.x);
    v.y = fmaf(ALPHA, xv.y - v.y, v.y);
    v.z = fmaf(ALPHA, xv.z - v.z, v.z);
    v.w = fmaf(ALPHA, xv.w - v.w, v.w);
    z.x = (v.x > V_TH) ? 1.f : 0.f;
    z.y = (v.y > V_TH) ? 1.f : 0.f;
    z.z = (v.z > V_TH) ? 1.f : 0.f;
    z.w = (v.w > V_TH) ? 1.f : 0.f;
    v.x = (z.x != 0.f) ? 0.f : v.x;
    v.y = (z.y != 0.f) ? 0.f : v.y;
    v.z = (z.z != 0.f) ? 0.f : v.z;
    v.w = (z.w != 0.f) ? 0.f : v.w;
}

__global__ __launch_bounds__(BLOCK)
void lif_encoder_kernel(const float* __restrict__ x,
                        float* __restrict__ out,
                        int n4 /* N/4 */, int n /* N */) {
    int i = blockIdx.x * blockDim.x + threadIdx.x;
    if (i >= n4) return;

    const int role = (blockIdx.y >= NCHUNKS) ? 1 : 0;  // 0 = voltages, 1 = spikes
    const int t0 = (blockIdx.y - role * NCHUNKS) * CHUNK;

    const float4 xv = reinterpret_cast<const float4*>(x)[i];
    const float xmax = fmaxf(fmaxf(xv.x, xv.y), fmaxf(xv.z, xv.w));

    // Stream base for this CTA's role (single contiguous output region).
    float4* sp = reinterpret_cast<float4*>(out)
                 + (size_t)role * SEQ_LENGTH * n4
                 + (size_t)t0 * n4 + i;

    if (xmax <= 1.0f) {
        if (role == 0) {
            // Voltage stream: v_t = x * (1 - 0.9^(t+1)).
            float p = exp2f((float)(t0 + 1) * LOG2_DECAY);   // 0.9^(t0+1)
            #pragma unroll
            for (int t = 0; t < CHUNK; ++t) {
                float4 v;
                v.x = fmaf(-p, xv.x, xv.x);
                v.y = fmaf(-p, xv.y, xv.y);
                v.z = fmaf(-p, xv.z, xv.z);
                v.w = fmaf(-p, xv.w, xv.w);
                __stcs(sp, v);
                p *= DECAY;
                sp += n4;
            }
        } else {
            // Spike stream: all zeros (no spikes for x <= 1).
            const float4 zero = make_float4(0.f, 0.f, 0.f, 0.f);
            #pragma unroll
            for (int t = 0; t < CHUNK; ++t) {
                __stcs(sp, zero);
                sp += n4;
            }
        }
    } else {
        // General path: exact replay recurrence (spiking possible).
        float4 v = make_float4(0.f, 0.f, 0.f, 0.f);
        float4 z;
        #pragma unroll 1
        for (int s = 0; s < t0; ++s)
            lif_step(v, xv, z);
        #pragma unroll
        for (int t = 0; t < CHUNK; ++t) {
            lif_step(v, xv, z);
            __stcs(sp, (role == 0) ? v : z);
            sp += n4;
        }
    }
}

extern "C" void kernel_launch(void* const* d_in, const int* in_sizes, int n_in,
                              void* d_out, int out_size) {
    const float* x = (const float*)d_in[0];
    float* out = (float*)d_out;
    int n = in_sizes[0];       // 262144
    int n4 = n / 4;            // 65536

    dim3 block(BLOCK);
    dim3 grid((n4 + BLOCK - 1) / BLOCK, 2 * NCHUNKS);
    lif_encoder_kernel<<<grid, block>>>(x, out, n4, n);
}